// round 6
// baseline (speedup 1.0000x reference)
#include <cuda_runtime.h>

#define TT   4096
#define NCH  32
#define NB   64
#define NP   511
#define PS   16
#define NTHREADS 512

// SMEM region layout (floats), dynamic shared:
//   sX   at 0        size 4096   (x, later a2)
//   A3   at 4096     size 4112   (a1 during stage2, then cA3)   base%32 = 0
//   D3   at 8208     size 4112   (cD3)                           base%32 = 16
//   D2   at 12320    size 4112   (cD2)                           base%32 = 0
//   D1   at 16432    size 4096   (cD1)                           base%32 = 16
#define OFF_X   0
#define OFF_A3  4096
#define OFF_D3  8208
#define OFF_D2  12320
#define OFF_D1  16432
#define SMEM_FLOATS 20528
#define BAND_STRIDE 4112

// Transposed input scratch: xT[b][n][t], contiguous in t.
__device__ float g_xT[(size_t)NB * NCH * TT];

// db4 decomposition filters (ptwt convention)
__device__ __constant__ float c_lo[8] = {
    -0.010597401784997278f,  0.032883011666982945f,  0.030841381835986965f,
    -0.18703481171888114f,  -0.02798376941698385f,   0.6308807679295904f,
     0.7148465705525415f,    0.23037781330885523f
};
__device__ __constant__ float c_hi[8] = {
    -0.23037781330885523f,   0.7148465705525415f,   -0.6308807679295904f,
    -0.02798376941698385f,   0.18703481171888114f,   0.030841381835986965f,
    -0.032883011666982945f, -0.010597401784997278f
};

// ---------------------------------------------------------------------------
// Kernel A: transpose (B, T, N) -> (B, N, T), float4 on both sides.
// ---------------------------------------------------------------------------
__global__ __launch_bounds__(256)
void transpose_kernel(const float* __restrict__ x)
{
    __shared__ float tile[32][33];
    const int b   = blockIdx.y;
    const int t0  = blockIdx.x << 5;
    const int lin = threadIdx.x;

    {
        const int t  = lin >> 3;
        const int n4 = (lin & 7) << 2;
        const float4 v = *(const float4*)&x[((size_t)b * TT + t0 + t) * NCH + n4];
        tile[t][n4 + 0] = v.x;
        tile[t][n4 + 1] = v.y;
        tile[t][n4 + 2] = v.z;
        tile[t][n4 + 3] = v.w;
    }
    __syncthreads();
    {
        const int n  = lin >> 3;
        const int t4 = (lin & 7) << 2;
        float4 v;
        v.x = tile[t4 + 0][n];
        v.y = tile[t4 + 1][n];
        v.z = tile[t4 + 2][n];
        v.w = tile[t4 + 3][n];
        *(float4*)&g_xT[((size_t)b * NCH + n) * TT + t0 + t4] = v;
    }
}

// ---------------------------------------------------------------------------
// One SWT stage, 4 outputs/thread: coef[t] = sum_j f[j]*in[(t+D*(4-j)) mod T]
// lo -> smemLo, hi -> smemHi (both full 4096-float band regions).
// ---------------------------------------------------------------------------
template<int D, int S, int W>
__device__ __forceinline__ void swt_stage(const float* __restrict__ in,
                                          float* __restrict__ smemLo,
                                          float* __restrict__ smemHi,
                                          int tid)
{
    #pragma unroll
    for (int k = 0; k < TT / 4 / NTHREADS; k++) {
        const int t0 = ((tid + k * NTHREADS) << 2);
        float w[W];
        #pragma unroll
        for (int q = 0; q < W / 4; q++) {
            const float4 v = *(const float4*)&in[(t0 + S + 4 * q + TT) & (TT - 1)];
            w[4 * q + 0] = v.x; w[4 * q + 1] = v.y;
            w[4 * q + 2] = v.z; w[4 * q + 3] = v.w;
        }
        float lo[4], hi[4];
        #pragma unroll
        for (int e = 0; e < 4; e++) {
            float l = 0.f, h = 0.f;
            #pragma unroll
            for (int j = 0; j < 8; j++) {
                const float v = w[e + D * (4 - j) - S];
                l = fmaf(c_lo[j], v, l);
                h = fmaf(c_hi[j], v, h);
            }
            lo[e] = l; hi[e] = h;
        }
        *(float4*)&smemLo[t0] = make_float4(lo[0], lo[1], lo[2], lo[3]);
        *(float4*)&smemHi[t0] = make_float4(hi[0], hi[1], hi[2], hi[3]);
    }
}

// ---------------------------------------------------------------------------
// Kernel B: per-(b,n) row — 3-level SWT staged in SMEM, then fully
// coalesced assembly write of the patched output.
// Output: out[((b*NP+p)*128 + n*4 + c)*16 + s]
//   line0 of (p,n): c0=cA3[8p+s], c1=cD3[8p+s]   (128B)
//   line1 of (p,n): c2=cD2[8p+s], c3=cD1[8p+s]   (128B)
// ---------------------------------------------------------------------------
__global__ __launch_bounds__(NTHREADS, 2)
void swt_patch_kernel(float* __restrict__ out)
{
    extern __shared__ __align__(16) float sm[];

    const int b   = blockIdx.x >> 5;
    const int n   = blockIdx.x & 31;
    const int tid = threadIdx.x;

    float* sX  = sm + OFF_X;
    float* sA3 = sm + OFF_A3;   // a1, then cA3
    float* sD3 = sm + OFF_D3;
    float* sD2 = sm + OFF_D2;
    float* sD1 = sm + OFF_D1;

    // Contiguous float4 load of the transposed row (L2-resident).
    const float4* xin = (const float4*)&g_xT[((size_t)b * NCH + n) * TT];
    #pragma unroll
    for (int k = 0; k < TT / 4 / NTHREADS; k++) {
        const int i = tid + k * NTHREADS;
        *(float4*)&sX[i << 2] = xin[i];
    }
    __syncthreads();

    // Level 1 (d=1): a1 -> sA3 region, cD1 -> sD1
    swt_stage<1, -4, 12>(sX, sA3, sD1, tid);
    __syncthreads();

    // Level 2 (d=2): a2 -> sX (x dead), cD2 -> sD2
    swt_stage<2, -8, 20>(sA3, sX, sD2, tid);
    __syncthreads();

    // Level 3 (d=4): cA3 -> sA3 (a1 dead), cD3 -> sD3
    swt_stage<4, -12, 32>(sX, sA3, sD3, tid);
    __syncthreads();

    // Assembly write: 511 patches x 2 lines x 8 float4 = 8176 float4 stores,
    // fully coalesced (4 consecutive lanes build one 128B line).
    // g -> p = g>>4, within = g&15:
    //   band = within>>2 (0:A3, 1:D3, 2:D2, 3:D1), s4 = (within&3)*4
    //   dst float offset = p*2048 + within*4
    float* dstBase = out + (size_t)b * NP * 2048 + (size_t)n * 64;
    const float* bands = sm + OFF_A3;
    for (int g = tid; g < NP * 16; g += NTHREADS) {
        const int p      = g >> 4;
        const int within = g & 15;
        const int band   = within >> 2;
        const int s4     = (within & 3) << 2;
        const float4 v = *(const float4*)&bands[band * BAND_STRIDE + (p << 3) + s4];
        *(float4*)&dstBase[(size_t)p * 2048 + (within << 2)] = v;
    }
}

extern "C" void kernel_launch(void* const* d_in, const int* in_sizes, int n_in,
                              void* d_out, int out_size)
{
    const float* x = (const float*)d_in[0];
    float* out = (float*)d_out;
    (void)in_sizes; (void)n_in; (void)out_size;

    static_assert(SMEM_FLOATS * 4 == 82112, "smem size");
    cudaFuncSetAttribute(swt_patch_kernel,
                         cudaFuncAttributeMaxDynamicSharedMemorySize,
                         SMEM_FLOATS * 4);

    dim3 tgrid(TT / 32, NB);
    transpose_kernel<<<tgrid, 256>>>(x);
    swt_patch_kernel<<<NB * NCH, NTHREADS, SMEM_FLOATS * 4>>>(out);
}

// round 8
// speedup vs baseline: 1.0027x; 1.0027x over previous
#include <cuda_runtime.h>

#define TT   4096
#define NCH  32
#define NB   64
#define NP   511
#define PS   16
#define NTHREADS 512

// 4 SMEM buffers, 4112 floats each (16-float skew => bases alternate 0/16 mod 32 banks)
//   B0 @ 0      (x, then a2)          base%32 = 0
//   B1 @ 4112   (a1, then cA3)        base%32 = 16
//   B2 @ 8224   (cD1, then cD3)       base%32 = 0
//   B3 @ 12336  (cD2)                 base%32 = 16
#define BUF_STRIDE 4112
#define SMEM_FLOATS (4 * BUF_STRIDE)
#define SMEM_BYTES  (SMEM_FLOATS * 4)

// Transposed input scratch: xT[b][n][t], contiguous in t.
__device__ float g_xT[(size_t)NB * NCH * TT];

// db4 decomposition filters (ptwt convention)
__device__ __constant__ float c_lo[8] = {
    -0.010597401784997278f,  0.032883011666982945f,  0.030841381835986965f,
    -0.18703481171888114f,  -0.02798376941698385f,   0.6308807679295904f,
     0.7148465705525415f,    0.23037781330885523f
};
__device__ __constant__ float c_hi[8] = {
    -0.23037781330885523f,   0.7148465705525415f,   -0.6308807679295904f,
    -0.02798376941698385f,   0.18703481171888114f,   0.030841381835986965f,
    -0.032883011666982945f, -0.010597401784997278f
};

// ---------------------------------------------------------------------------
// Kernel A: transpose (B, T, N) -> (B, N, T), float4 on both sides.
// ---------------------------------------------------------------------------
__global__ __launch_bounds__(256)
void transpose_kernel(const float* __restrict__ x)
{
    __shared__ float tile[32][33];
    const int b   = blockIdx.y;
    const int t0  = blockIdx.x << 5;
    const int lin = threadIdx.x;

    {
        const int t  = lin >> 3;
        const int n4 = (lin & 7) << 2;
        const float4 v = *(const float4*)&x[((size_t)b * TT + t0 + t) * NCH + n4];
        tile[t][n4 + 0] = v.x;
        tile[t][n4 + 1] = v.y;
        tile[t][n4 + 2] = v.z;
        tile[t][n4 + 3] = v.w;
    }
    __syncthreads();
    {
        const int n  = lin >> 3;
        const int t4 = (lin & 7) << 2;
        float4 v;
        v.x = tile[t4 + 0][n];
        v.y = tile[t4 + 1][n];
        v.z = tile[t4 + 2][n];
        v.w = tile[t4 + 3][n];
        *(float4*)&g_xT[((size_t)b * NCH + n) * TT + t0 + t4] = v;
    }
}

// ---------------------------------------------------------------------------
// One SWT stage, 4 outputs/thread: coef[t] = sum_j f[j]*in[(t+D*(4-j)) mod T]
// ---------------------------------------------------------------------------
template<int D, int S, int W>
__device__ __forceinline__ void swt_stage(const float* __restrict__ in,
                                          float* __restrict__ smemLo,
                                          float* __restrict__ smemHi,
                                          int tid)
{
    #pragma unroll
    for (int k = 0; k < TT / 4 / NTHREADS; k++) {
        const int t0 = ((tid + k * NTHREADS) << 2);
        float w[W];
        #pragma unroll
        for (int q = 0; q < W / 4; q++) {
            const float4 v = *(const float4*)&in[(t0 + S + 4 * q + TT) & (TT - 1)];
            w[4 * q + 0] = v.x; w[4 * q + 1] = v.y;
            w[4 * q + 2] = v.z; w[4 * q + 3] = v.w;
        }
        float lo[4], hi[4];
        #pragma unroll
        for (int e = 0; e < 4; e++) {
            float l = 0.f, h = 0.f;
            #pragma unroll
            for (int j = 0; j < 8; j++) {
                const float v = w[e + D * (4 - j) - S];
                l = fmaf(c_lo[j], v, l);
                h = fmaf(c_hi[j], v, h);
            }
            lo[e] = l; hi[e] = h;
        }
        *(float4*)&smemLo[t0] = make_float4(lo[0], lo[1], lo[2], lo[3]);
        *(float4*)&smemHi[t0] = make_float4(hi[0], hi[1], hi[2], hi[3]);
    }
}

// ---------------------------------------------------------------------------
// Write one 128B-line family for all patches:
//   lineOff = 0  -> channels 0,1 (bandLo=cA3, bandHi=cD3)
//   lineOff = 32 -> channels 2,3 (bandLo=cD2, bandHi=cD1)
// dst float offset = p*2048 + lineOff + w8*4 ; src = band[8p + s4]
// 8 consecutive threads produce one contiguous 128B line; fully coalesced.
// ---------------------------------------------------------------------------
__device__ __forceinline__ void write_lines(const float* __restrict__ bandLo,
                                            const float* __restrict__ bandHi,
                                            float* __restrict__ dstBase,
                                            int lineOff, int tid)
{
    for (int g = tid; g < NP * 8; g += NTHREADS) {
        const int p  = g >> 3;
        const int w8 = g & 7;
        const int s4 = (w8 & 3) << 2;
        const float* src = (w8 < 4) ? bandLo : bandHi;
        const float4 v = *(const float4*)&src[(p << 3) + s4];
        *(float4*)&dstBase[(size_t)p * 2048 + lineOff + (w8 << 2)] = v;
    }
}

// ---------------------------------------------------------------------------
// Kernel B: per-(b,n) row — 3-level SWT staged in 4 SMEM buffers; the
// [cD2|cD1] lines are flushed after stage 2 so stage 3 can reuse buffers.
// 65.8 KB dynamic smem => 3 blocks/SM (48 warps) on the 228 KB carveout.
// ---------------------------------------------------------------------------
__global__ __launch_bounds__(NTHREADS)
void swt_patch_kernel(float* __restrict__ out)
{
    extern __shared__ __align__(16) float sm[];

    const int b   = blockIdx.x >> 5;
    const int n   = blockIdx.x & 31;
    const int tid = threadIdx.x;

    float* B0 = sm;                   // x   -> a2
    float* B1 = sm + 1 * BUF_STRIDE;  // a1  -> cA3
    float* B2 = sm + 2 * BUF_STRIDE;  // cD1 -> cD3
    float* B3 = sm + 3 * BUF_STRIDE;  // cD2

    // Phase L: contiguous float4 load of the transposed row (L2-resident).
    const float4* xin = (const float4*)&g_xT[((size_t)b * NCH + n) * TT];
    #pragma unroll
    for (int k = 0; k < TT / 4 / NTHREADS; k++) {
        const int i = tid + k * NTHREADS;
        *(float4*)&B0[i << 2] = xin[i];
    }
    __syncthreads();

    // Phase 1 (d=1): a1 -> B1, cD1 -> B2
    swt_stage<1, -4, 12>(B0, B1, B2, tid);
    __syncthreads();

    // Phase 2 (d=2): a2 -> B0 (x dead), cD2 -> B3
    swt_stage<2, -8, 20>(B1, B0, B3, tid);
    __syncthreads();

    // Phase 3: flush [cD2|cD1] lines (channels 2,3)
    float* dstBase = out + (size_t)b * NP * 2048 + (size_t)n * 64;
    write_lines(B3, B2, dstBase, 32, tid);
    __syncthreads();

    // Phase 4 (d=4): cA3 -> B1 (a1 dead), cD3 -> B2 (cD1 flushed)
    swt_stage<4, -12, 32>(B0, B1, B2, tid);
    __syncthreads();

    // Phase 5: flush [cA3|cD3] lines (channels 0,1)
    write_lines(B1, B2, dstBase, 0, tid);
}

extern "C" void kernel_launch(void* const* d_in, const int* in_sizes, int n_in,
                              void* d_out, int out_size)
{
    const float* x = (const float*)d_in[0];
    float* out = (float*)d_out;
    (void)in_sizes; (void)n_in; (void)out_size;

    cudaFuncSetAttribute(swt_patch_kernel,
                         cudaFuncAttributeMaxDynamicSharedMemorySize,
                         SMEM_BYTES);

    dim3 tgrid(TT / 32, NB);
    transpose_kernel<<<tgrid, 256>>>(x);
    swt_patch_kernel<<<NB * NCH, NTHREADS, SMEM_BYTES>>>(out);
}

// round 9
// speedup vs baseline: 1.1010x; 1.0981x over previous
#include <cuda_runtime.h>

#define TT   4096
#define NCH  32
#define NB   64
#define NP   511
#define PS   16
#define NTHREADS 512

// 4 SMEM buffers, 4112 floats each (16-float skew => bases alternate 0/16 mod 32 banks)
//   B0 @ 0      (x, then a2)          base%32 = 0
//   B1 @ 4112   (a1, then cA3)        base%32 = 16
//   B2 @ 8224   (cD1, then cD3)       base%32 = 0
//   B3 @ 12336  (cD2)                 base%32 = 16
#define BUF_STRIDE 4112
#define SMEM_FLOATS (4 * BUF_STRIDE)
#define SMEM_BYTES  (SMEM_FLOATS * 4)

// Transposed input scratch: xT[b][n][t], contiguous in t.
__device__ float g_xT[(size_t)NB * NCH * TT];

// db4 decomposition filters (ptwt convention)
__device__ __constant__ float c_lo[8] = {
    -0.010597401784997278f,  0.032883011666982945f,  0.030841381835986965f,
    -0.18703481171888114f,  -0.02798376941698385f,   0.6308807679295904f,
     0.7148465705525415f,    0.23037781330885523f
};
__device__ __constant__ float c_hi[8] = {
    -0.23037781330885523f,   0.7148465705525415f,   -0.6308807679295904f,
    -0.02798376941698385f,   0.18703481171888114f,   0.030841381835986965f,
    -0.032883011666982945f, -0.010597401784997278f
};

// ---------------------------------------------------------------------------
// Kernel A: transpose (B, T, N) -> (B, N, T), float4 on both sides.
// ---------------------------------------------------------------------------
__global__ __launch_bounds__(256)
void transpose_kernel(const float* __restrict__ x)
{
    __shared__ float tile[32][33];
    const int b   = blockIdx.y;
    const int t0  = blockIdx.x << 5;
    const int lin = threadIdx.x;

    {
        const int t  = lin >> 3;
        const int n4 = (lin & 7) << 2;
        const float4 v = *(const float4*)&x[((size_t)b * TT + t0 + t) * NCH + n4];
        tile[t][n4 + 0] = v.x;
        tile[t][n4 + 1] = v.y;
        tile[t][n4 + 2] = v.z;
        tile[t][n4 + 3] = v.w;
    }
    __syncthreads();
    {
        const int n  = lin >> 3;
        const int t4 = (lin & 7) << 2;
        float4 v;
        v.x = tile[t4 + 0][n];
        v.y = tile[t4 + 1][n];
        v.z = tile[t4 + 2][n];
        v.w = tile[t4 + 3][n];
        *(float4*)&g_xT[((size_t)b * NCH + n) * TT + t0 + t4] = v;
    }
}

// ---------------------------------------------------------------------------
// One SWT stage, 4 outputs/thread, streaming-accumulate form (low reg
// pressure): coef[e] = sum_j f[j]*in[t0 + e + D*(4-j)], e in [0,4).
// Each window element at relative offset a contributes to output e iff
// (a - e) % D == 0 and j = 4 - (a-e)/D in [0,8). All pruned at compile time.
// ---------------------------------------------------------------------------
template<int D, int S, int W>
__device__ __forceinline__ void swt_stage(const float* __restrict__ in,
                                          float* __restrict__ smemLo,
                                          float* __restrict__ smemHi,
                                          int tid)
{
    #pragma unroll
    for (int k = 0; k < TT / 4 / NTHREADS; k++) {
        const int t0 = ((tid + k * NTHREADS) << 2);
        float lo[4] = {0.f, 0.f, 0.f, 0.f};
        float hi[4] = {0.f, 0.f, 0.f, 0.f};
        #pragma unroll
        for (int q = 0; q < W / 4; q++) {
            const float4 v = *(const float4*)&in[(t0 + S + 4 * q + TT) & (TT - 1)];
            const float elem[4] = {v.x, v.y, v.z, v.w};
            #pragma unroll
            for (int idx = 0; idx < 4; idx++) {
                const int a = S + 4 * q + idx;   // offset relative to t0
                #pragma unroll
                for (int e = 0; e < 4; e++) {
                    const int diff = a - e;
                    if (diff % D == 0) {
                        const int j = 4 - diff / D;
                        if (j >= 0 && j < 8) {
                            lo[e] = fmaf(c_lo[j], elem[idx], lo[e]);
                            hi[e] = fmaf(c_hi[j], elem[idx], hi[e]);
                        }
                    }
                }
            }
        }
        *(float4*)&smemLo[t0] = make_float4(lo[0], lo[1], lo[2], lo[3]);
        *(float4*)&smemHi[t0] = make_float4(hi[0], hi[1], hi[2], hi[3]);
    }
}

// ---------------------------------------------------------------------------
// Write one 128B-line family for all patches:
//   lineOff = 0  -> channels 0,1 (bandLo=cA3, bandHi=cD3)
//   lineOff = 32 -> channels 2,3 (bandLo=cD2, bandHi=cD1)
// 8 consecutive threads produce one contiguous 128B line; fully coalesced.
// ---------------------------------------------------------------------------
__device__ __forceinline__ void write_lines(const float* __restrict__ bandLo,
                                            const float* __restrict__ bandHi,
                                            float* __restrict__ dstBase,
                                            int lineOff, int tid)
{
    for (int g = tid; g < NP * 8; g += NTHREADS) {
        const int p  = g >> 3;
        const int w8 = g & 7;
        const int s4 = (w8 & 3) << 2;
        const float* src = (w8 < 4) ? bandLo : bandHi;
        const float4 v = *(const float4*)&src[(p << 3) + s4];
        *(float4*)&dstBase[(size_t)p * 2048 + lineOff + (w8 << 2)] = v;
    }
}

// ---------------------------------------------------------------------------
// Kernel B: per-(b,n) row — 3-level SWT staged in 4 SMEM buffers; the
// [cD2|cD1] lines are flushed after stage 2 so stage 3 can reuse buffers.
// 65.8 KB smem x 3 blocks = 197 KB <= 228 KB; minBlocks=3 caps regs at 40
// so the register file (65536/SM) also admits 3 blocks (48 warps).
// ---------------------------------------------------------------------------
__global__ __launch_bounds__(NTHREADS, 3)
void swt_patch_kernel(float* __restrict__ out)
{
    extern __shared__ __align__(16) float sm[];

    const int b   = blockIdx.x >> 5;
    const int n   = blockIdx.x & 31;
    const int tid = threadIdx.x;

    float* B0 = sm;                   // x   -> a2
    float* B1 = sm + 1 * BUF_STRIDE;  // a1  -> cA3
    float* B2 = sm + 2 * BUF_STRIDE;  // cD1 -> cD3
    float* B3 = sm + 3 * BUF_STRIDE;  // cD2

    // Phase L: contiguous float4 load of the transposed row (L2-resident).
    const float4* xin = (const float4*)&g_xT[((size_t)b * NCH + n) * TT];
    #pragma unroll
    for (int k = 0; k < TT / 4 / NTHREADS; k++) {
        const int i = tid + k * NTHREADS;
        *(float4*)&B0[i << 2] = xin[i];
    }
    __syncthreads();

    // Phase 1 (d=1): a1 -> B1, cD1 -> B2
    swt_stage<1, -4, 12>(B0, B1, B2, tid);
    __syncthreads();

    // Phase 2 (d=2): a2 -> B0 (x dead), cD2 -> B3
    swt_stage<2, -8, 20>(B1, B0, B3, tid);
    __syncthreads();

    // Phase 3: flush [cD2|cD1] lines (channels 2,3)
    float* dstBase = out + (size_t)b * NP * 2048 + (size_t)n * 64;
    write_lines(B3, B2, dstBase, 32, tid);
    __syncthreads();

    // Phase 4 (d=4): cA3 -> B1 (a1 dead), cD3 -> B2 (cD1 flushed)
    swt_stage<4, -12, 32>(B0, B1, B2, tid);
    __syncthreads();

    // Phase 5: flush [cA3|cD3] lines (channels 0,1)
    write_lines(B1, B2, dstBase, 0, tid);
}

extern "C" void kernel_launch(void* const* d_in, const int* in_sizes, int n_in,
                              void* d_out, int out_size)
{
    const float* x = (const float*)d_in[0];
    float* out = (float*)d_out;
    (void)in_sizes; (void)n_in; (void)out_size;

    cudaFuncSetAttribute(swt_patch_kernel,
                         cudaFuncAttributeMaxDynamicSharedMemorySize,
                         SMEM_BYTES);

    dim3 tgrid(TT / 32, NB);
    transpose_kernel<<<tgrid, 256>>>(x);
    swt_patch_kernel<<<NB * NCH, NTHREADS, SMEM_BYTES>>>(out);
}